// round 12
// baseline (speedup 1.0000x reference)
#include <cuda_runtime.h>
#include <cuda_bf16.h>
#include <cuda_fp16.h>
#include <math.h>
#include <cstdint>

#define NV 50000
#define EE 800000
#define ET (EE + NV)
#define HEADS 4
#define D1 256
#define KTOT 768

typedef unsigned long long ull;

// ---------------- scratch ------------------------------------------------------
__device__ __half g_xh1h[(size_t)NV * D1];
__device__ __half g_xh2h[(size_t)NV * 64];
__device__ __nv_bfloat16 g_xb[(size_t)NV * 512];
__device__ __nv_bfloat16 g_h2b[(size_t)NV * 512];
__device__ __nv_bfloat16 g_w1b[256 * KTOT];
__device__ __nv_bfloat16 g_w2b[64 * KTOT];
__device__ float g_als1[NV * HEADS], g_ald1[NV * HEADS];
__device__ float g_als2[NV], g_ald2[NV];
__device__ float g_t1[(size_t)ET * HEADS];
__device__ float g_t2[ET];
__device__ int g_rowptr[NV + 1], g_deg[NV], g_elist[ET];

// ---------------- helpers ------------------------------------------------------
__device__ __forceinline__ float lrelu(float v) { return v > 0.f ? v : 0.2f * v; }
__device__ __forceinline__ void edge_sd(const int* __restrict__ ei, int e, int& s, int& d) {
    if (e < EE) { s = ei[e]; d = ei[EE + e]; } else { s = e - EE; d = s; }
}
#define FMA2(acc, a, b) asm("fma.rn.f32x2 %0, %1, %2, %3;" : "=l"(acc) : "l"(a), "l"(b), "l"(acc))
#define PACK2(o, v)     asm("mov.b64 %0, {%1, %1};" : "=l"(o) : "r"(__float_as_uint(v)))
#define UNPACK2(l, h, i) asm("mov.b64 {%0, %1}, %2;" : "=r"(l), "=r"(h) : "l"(i))

__device__ __forceinline__ uint32_t smem_u32(const void* p) {
    uint32_t a;
    asm("{ .reg .u64 t; cvta.to.shared.u64 t, %1; cvt.u32.u64 %0, t; }" : "=r"(a) : "l"(p));
    return a;
}
#define CP16(dst, src) asm volatile("cp.async.ca.shared.global [%0], [%1], 16;" :: "r"(dst), "l"(src))
#define CPCOMMIT()     asm volatile("cp.async.commit_group;" ::: "memory")
#define CPWAIT(n)      asm volatile("cp.async.wait_group %0;" :: "n"(n) : "memory")

// ---------------- conversions ----------------------------------------------------
__global__ void convW(const float* __restrict__ W, __nv_bfloat16* __restrict__ Bt, int Nc) {
    int i = blockIdx.x * blockDim.x + threadIdx.x;
    if (i >= 256 * Nc) return;
    int k = i / Nc, n = i % Nc;
    float w = W[k * Nc + n];
    __nv_bfloat16 hi = __float2bfloat16_rn(w);
    __nv_bfloat16 lo = __float2bfloat16_rn(w - __bfloat162float(hi));
    Bt[(size_t)n * KTOT + k] = hi;
    Bt[(size_t)n * KTOT + 256 + k] = hi;
    Bt[(size_t)n * KTOT + 512 + k] = lo;
}
__global__ void convX(const float* __restrict__ x, __nv_bfloat16* __restrict__ xb) {
    int i = blockIdx.x * blockDim.x + threadIdx.x;
    if (i >= NV * 64) return;
    int node = i >> 6, c = (i & 63) * 4;
    float4 f = *(const float4*)&x[(size_t)node * 256 + c];
    float ff[4] = {f.x, f.y, f.z, f.w};
    __nv_bfloat16 hb[4], lb[4];
#pragma unroll
    for (int e = 0; e < 4; e++) {
        hb[e] = __float2bfloat16_rn(ff[e]);
        lb[e] = __float2bfloat16_rn(ff[e] - __bfloat162float(hb[e]));
    }
    *(ull*)&xb[(size_t)node * 512 + c] = *(ull*)hb;
    *(ull*)&xb[(size_t)node * 512 + 256 + c] = *(ull*)lb;
}

// ---------------- CSR build --------------------------------------------------------
__global__ void deg_init() { int i = blockIdx.x * blockDim.x + threadIdx.x; if (i < NV) g_deg[i] = 1; }
__global__ void deg_hist(const int* __restrict__ ei) {
    int e = blockIdx.x * blockDim.x + threadIdx.x;
    if (e < EE) atomicAdd(&g_deg[ei[EE + e]], 1);
}
__global__ void scan_k() {
    __shared__ int ssum[1024];
    const int CH = (NV + 1023) / 1024;
    int t = threadIdx.x, base = t * CH, s = 0;
    for (int j = 0; j < CH; j++) { int i = base + j; if (i < NV) s += g_deg[i]; }
    ssum[t] = s; __syncthreads();
    for (int off = 1; off < 1024; off <<= 1) {
        int v = (t >= off) ? ssum[t - off] : 0;
        __syncthreads(); ssum[t] += v; __syncthreads();
    }
    int off = (t == 0) ? 0 : ssum[t - 1];
    for (int j = 0; j < CH; j++) {
        int i = base + j;
        if (i < NV) { int d = g_deg[i]; g_rowptr[i] = off; g_deg[i] = off; off += d; }
    }
    if (t == 0) g_rowptr[NV] = ET;
}
__global__ void scatter_k(const int* __restrict__ ei) {
    int e = blockIdx.x * blockDim.x + threadIdx.x;
    if (e >= ET) return;
    int s, d; edge_sd(ei, e, s, d);
    g_elist[atomicAdd(&g_deg[d], 1)] = s;
}

// ---------------- mma.sync bf16 GEMM + fused attention dots -------------------------
template <int H>
__global__ __launch_bounds__(256) void gemm_mma(
    const __nv_bfloat16* __restrict__ Ab, const __nv_bfloat16* __restrict__ Bt,
    __half* __restrict__ Ch, const float* __restrict__ asrc, const float* __restrict__ adst,
    float* __restrict__ als, float* __restrict__ ald, int M, int NTOT) {
    __shared__ __align__(16) __nv_bfloat16 sA[2][128 * 40];
    __shared__ __align__(16) __nv_bfloat16 sB[2][64 * 40];
    __shared__ float sdot[128][2];
    int tid = threadIdx.x, lane = tid & 31, w = tid >> 5;
    int wm = w & 3, wn = w >> 2;
    int rowBase = blockIdx.y * 128, n0 = blockIdx.x * 64;

    uint32_t sAa = smem_u32(&sA[0][0]);
    uint32_t sBa = smem_u32(&sB[0][0]);

    int arow = tid >> 1, aseg = (tid & 1) * 16;
    int brow = tid >> 2, bseg = (tid & 3) * 8;
    const __nv_bfloat16* Asrc = Ab + (size_t)min(rowBase + arow, M - 1) * 512 + aseg;
    const __nv_bfloat16* Bsrc = Bt + (size_t)(n0 + brow) * KTOT + bseg;
    uint32_t Adst = sAa + arow * 80 + aseg * 2;
    uint32_t Bdst = sBa + brow * 80 + bseg * 2;

#define ISSUE(s) do { \
    int _b = (s) & 1; int _k0 = (s) * 32; \
    int _ac = (_k0 < 512) ? _k0 : _k0 - 512; \
    CP16(Adst + _b * 10240, Asrc + _ac); \
    CP16(Adst + _b * 10240 + 16, Asrc + _ac + 8); \
    CP16(Bdst + _b * 5120, Bsrc + _k0); \
} while (0)

    float acc[2][4][4];
#pragma unroll
    for (int i = 0; i < 2; i++)
#pragma unroll
        for (int j = 0; j < 4; j++)
#pragma unroll
            for (int q = 0; q < 4; q++) acc[i][j][q] = 0.f;

    ISSUE(0); CPCOMMIT();
    for (int s = 0; s < 24; s++) {
        if (s < 23) { ISSUE(s + 1); CPCOMMIT(); CPWAIT(1); }
        else        { CPWAIT(0); }
        __syncthreads();
        int b = s & 1;
        uint32_t baseA = sAa + b * 10240;
        uint32_t baseB = sBa + b * 5120;
#pragma unroll
        for (int kt = 0; kt < 2; kt++) {
            uint32_t a[2][4], bb[4][2];
#pragma unroll
            for (int mt = 0; mt < 2; mt++) {
                uint32_t addr = baseA + (wm * 32 + mt * 16 + (lane & 15)) * 80 +
                                kt * 32 + (lane >> 4) * 16;
                asm volatile("ldmatrix.sync.aligned.m8n8.x4.shared.b16 {%0,%1,%2,%3}, [%4];"
                             : "=r"(a[mt][0]), "=r"(a[mt][1]), "=r"(a[mt][2]), "=r"(a[mt][3])
                             : "r"(addr));
            }
#pragma unroll
            for (int nt = 0; nt < 4; nt++) {
                uint32_t addr = baseB + (wn * 32 + nt * 8 + (lane & 7)) * 80 +
                                kt * 32 + ((lane >> 3) & 1) * 16;
                asm volatile("ldmatrix.sync.aligned.m8n8.x2.shared.b16 {%0,%1}, [%2];"
                             : "=r"(bb[nt][0]), "=r"(bb[nt][1]) : "r"(addr));
            }
#pragma unroll
            for (int mt = 0; mt < 2; mt++)
#pragma unroll
                for (int nt = 0; nt < 4; nt++)
                    asm volatile(
                        "mma.sync.aligned.m16n8k16.row.col.f32.bf16.bf16.f32 "
                        "{%0,%1,%2,%3}, {%4,%5,%6,%7}, {%8,%9}, {%0,%1,%2,%3};"
                        : "+f"(acc[mt][nt][0]), "+f"(acc[mt][nt][1]),
                          "+f"(acc[mt][nt][2]), "+f"(acc[mt][nt][3])
                        : "r"(a[mt][0]), "r"(a[mt][1]), "r"(a[mt][2]), "r"(a[mt][3]),
                          "r"(bb[nt][0]), "r"(bb[nt][1]));
        }
        __syncthreads();
    }
#undef ISSUE

    sdot[tid >> 1][tid & 1] = 0.f;
    __syncthreads();
    int g = lane >> 2, tg = lane & 3;
    float as_[8], ad_[8];
#pragma unroll
    for (int nt = 0; nt < 4; nt++)
#pragma unroll
        for (int j = 0; j < 2; j++) {
            int col = n0 + wn * 32 + nt * 8 + tg * 2 + j;
            as_[nt * 2 + j] = asrc[col];
            ad_[nt * 2 + j] = adst[col];
        }
#pragma unroll
    for (int mt = 0; mt < 2; mt++) {
        int r0l = wm * 32 + mt * 16 + g, r1l = r0l + 8;
        int r0 = rowBase + r0l, r1 = rowBase + r1l;
        float s0 = 0.f, d0 = 0.f, s1 = 0.f, d1 = 0.f;
#pragma unroll
        for (int nt = 0; nt < 4; nt++) {
#pragma unroll
            for (int j = 0; j < 2; j++) {
                s0 += acc[mt][nt][j] * as_[nt * 2 + j];
                d0 += acc[mt][nt][j] * ad_[nt * 2 + j];
                s1 += acc[mt][nt][2 + j] * as_[nt * 2 + j];
                d1 += acc[mt][nt][2 + j] * ad_[nt * 2 + j];
            }
            int col = n0 + wn * 32 + nt * 8 + tg * 2;
            if (r0 < M) *(__half2*)&Ch[(size_t)r0 * NTOT + col] =
                __floats2half2_rn(acc[mt][nt][0], acc[mt][nt][1]);
            if (r1 < M) *(__half2*)&Ch[(size_t)r1 * NTOT + col] =
                __floats2half2_rn(acc[mt][nt][2], acc[mt][nt][3]);
        }
#pragma unroll
        for (int o = 1; o <= 2; o <<= 1) {
            s0 += __shfl_xor_sync(~0u, s0, o); d0 += __shfl_xor_sync(~0u, d0, o);
            s1 += __shfl_xor_sync(~0u, s1, o); d1 += __shfl_xor_sync(~0u, d1, o);
        }
        if (tg == 0) {
            atomicAdd(&sdot[r0l][0], s0); atomicAdd(&sdot[r0l][1], d0);
            atomicAdd(&sdot[r1l][0], s1); atomicAdd(&sdot[r1l][1], d1);
        }
    }
    __syncthreads();
    if (tid < 128) {
        int r = rowBase + tid;
        if (r < M) {
            int head = blockIdx.x;
            als[(size_t)r * H + head] = sdot[tid][0];
            ald[(size_t)r * H + head] = sdot[tid][1];
        }
    }
}

// ---------------- agg layer1: 2 warps/node, fixed-8 clamped chunks, fp16 gather ------
__global__ void gat_agg1(const __half* __restrict__ xh, const float* __restrict__ als,
                         const float* __restrict__ ald, const float* __restrict__ bias,
                         __nv_bfloat16* __restrict__ h2b) {
    int gw = (blockIdx.x * blockDim.x + threadIdx.x) >> 5;
    int node = gw >> 1, hp = gw & 1;
    if (node >= NV) return;
    int lane = threadIdx.x & 31;
    int beg = g_rowptr[node], end = g_rowptr[node + 1];
    float2 av = *(const float2*)&ald[node * 4 + 2 * hp];

    float d0 = 0.f, d1 = 0.f;
    for (int j = beg + lane; j < end; j += 32) {
        float2 a = *(const float2*)&als[g_elist[j] * 4 + 2 * hp];
        float t0 = __expf(lrelu(a.x + av.x)), t1 = __expf(lrelu(a.y + av.y));
        *(float2*)&g_t1[(size_t)j * 4 + 2 * hp] = make_float2(t0, t1);
        d0 += t0; d1 += t1;
    }
#pragma unroll
    for (int o = 16; o; o >>= 1) {
        d0 += __shfl_xor_sync(~0u, d0, o);
        d1 += __shfl_xor_sync(~0u, d1, o);
    }
    int hl = lane >> 4;
    int myhead = hp * 2 + hl;
    float myinv = 1.f / ((hl ? d1 : d0) + 1e-16f);
    __syncwarp();

    int c0 = hp * 128 + lane * 4;
    ull acc[2] = {0, 0};
    for (int j0 = beg; j0 < end; j0 += 32) {
        int cnt = min(32, end - j0);
        int sv = g_elist[j0 + min(lane, cnt - 1)];
        for (int k0 = 0; k0 < cnt; k0 += 8) {
#pragma unroll
            for (int q = 0; q < 8; q++) {
                int k = k0 + q;
                int kc = min(k, cnt - 1);
                int s = __shfl_sync(~0u, sv, kc);
                float t = g_t1[(size_t)(j0 + kc) * 4 + myhead];
                t = (k < cnt) ? t : 0.f;
                ull wd; PACK2(wd, t);
                uint2 v = *(const uint2*)(xh + (size_t)s * 256 + c0);
                float2 f0 = __half22float2(*(__half2*)&v.x);
                float2 f1 = __half22float2(*(__half2*)&v.y);
                FMA2(acc[0], *(ull*)&f0, wd);
                FMA2(acc[1], *(ull*)&f1, wd);
            }
        }
    }
    float o[4];
#pragma unroll
    for (int i = 0; i < 2; i++) {
        unsigned lo_, hi_;
        UNPACK2(lo_, hi_, acc[i]);
        float v0 = __uint_as_float(lo_) * myinv + bias[c0 + 2 * i];
        float v1 = __uint_as_float(hi_) * myinv + bias[c0 + 2 * i + 1];
        o[2 * i] = v0 > 0.f ? v0 : expm1f(v0);
        o[2 * i + 1] = v1 > 0.f ? v1 : expm1f(v1);
    }
    __nv_bfloat16 hb[4], lb[4];
#pragma unroll
    for (int i = 0; i < 4; i++) {
        hb[i] = __float2bfloat16_rn(o[i]);
        lb[i] = __float2bfloat16_rn(o[i] - __bfloat162float(hb[i]));
    }
    *(ull*)&h2b[(size_t)node * 512 + c0] = *(ull*)hb;
    *(ull*)&h2b[(size_t)node * 512 + 256 + c0] = *(ull*)lb;
}

// ---------------- agg layer2: warp/node, fixed-8 clamped chunks, fp16 gather ---------
__global__ void gat_agg2(const __half* __restrict__ xh, const float* __restrict__ als,
                         const float* __restrict__ ald, const float* __restrict__ bias,
                         float* __restrict__ out) {
    int node = (blockIdx.x * blockDim.x + threadIdx.x) >> 5;
    if (node >= NV) return;
    int lane = threadIdx.x & 31;
    int beg = g_rowptr[node], end = g_rowptr[node + 1];
    float av = ald[node];

    float den = 0.f;
    for (int j = beg + lane; j < end; j += 32) {
        float t = __expf(lrelu(als[g_elist[j]] + av));
        g_t2[j] = t; den += t;
    }
#pragma unroll
    for (int o = 16; o; o >>= 1) den += __shfl_xor_sync(~0u, den, o);
    float inv = 1.f / (den + 1e-16f);
    __syncwarp();

    ull acc = 0;
    for (int j0 = beg; j0 < end; j0 += 32) {
        int cnt = min(32, end - j0);
        int cl = min(lane, cnt - 1);
        int sv = g_elist[j0 + cl];
        float tv = g_t2[j0 + cl];
        for (int k0 = 0; k0 < cnt; k0 += 8) {
#pragma unroll
            for (int q = 0; q < 8; q++) {
                int k = k0 + q;
                int kc = min(k, cnt - 1);
                int s = __shfl_sync(~0u, sv, kc);
                float t = __shfl_sync(~0u, tv, kc);
                t = (k < cnt) ? t : 0.f;
                ull wd; PACK2(wd, t);
                uint32_t v = *(const uint32_t*)(xh + (size_t)s * 64 + lane * 2);
                float2 f = __half22float2(*(__half2*)&v);
                FMA2(acc, *(ull*)&f, wd);
            }
        }
    }
    unsigned lo, hi;
    UNPACK2(lo, hi, acc);
    int c = lane * 2;
    float v0 = __uint_as_float(lo) * inv + bias[c];
    float v1 = __uint_as_float(hi) * inv + bias[c + 1];
    *(float2*)(out + (size_t)node * 64 + c) =
        make_float2(v0 > 0.f ? v0 : expm1f(v0), v1 > 0.f ? v1 : expm1f(v1));
}

// ---------------- launch ---------------------------------------------------------------
extern "C" void kernel_launch(void* const* d_in, const int* in_sizes, int n_in,
                              void* d_out, int out_size) {
    const float* x     = (const float*)d_in[0];
    const int*   ei    = (const int*)d_in[1];
    const float* W1    = (const float*)d_in[2];
    const float* asrc1 = (const float*)d_in[3];
    const float* adst1 = (const float*)d_in[4];
    const float* b1    = (const float*)d_in[5];
    const float* W2    = (const float*)d_in[6];
    const float* asrc2 = (const float*)d_in[7];
    const float* adst2 = (const float*)d_in[8];
    const float* b2    = (const float*)d_in[9];
    float* out = (float*)d_out;

    float *als1, *ald1, *als2, *ald2;
    __half *xh1h, *xh2h;
    __nv_bfloat16 *w1b, *w2b, *xb, *h2b;
    cudaGetSymbolAddress((void**)&xh1h, g_xh1h);
    cudaGetSymbolAddress((void**)&xh2h, g_xh2h);
    cudaGetSymbolAddress((void**)&als1, g_als1);
    cudaGetSymbolAddress((void**)&ald1, g_ald1);
    cudaGetSymbolAddress((void**)&als2, g_als2);
    cudaGetSymbolAddress((void**)&ald2, g_ald2);
    cudaGetSymbolAddress((void**)&w1b, g_w1b);
    cudaGetSymbolAddress((void**)&w2b, g_w2b);
    cudaGetSymbolAddress((void**)&xb, g_xb);
    cudaGetSymbolAddress((void**)&h2b, g_h2b);

    static cudaStream_t sCsr = nullptr;
    static cudaEvent_t ev0 = nullptr, ev1 = nullptr;
    if (!sCsr) {
        cudaStreamCreateWithFlags(&sCsr, cudaStreamNonBlocking);
        cudaEventCreateWithFlags(&ev0, cudaEventDisableTiming);
        cudaEventCreateWithFlags(&ev1, cudaEventDisableTiming);
    }

    const int TB = 256;

    // fork event for side stream
    cudaEventRecord(ev0, 0);
    cudaStreamWaitEvent(sCsr, ev0, 0);

    // ---- main chain enqueued FIRST so gemm1 is the 4th launch (profiled slot) ----
    convX<<<(NV * 64 + TB - 1) / TB, TB>>>(x, xb);                       // 1
    convW<<<(256 * 256 + TB - 1) / TB, TB>>>(W1, w1b, 256);              // 2
    convW<<<(256 * 64 + TB - 1) / TB, TB>>>(W2, w2b, 64);                // 3
    gemm_mma<4><<<dim3(4, (NV + 127) / 128), 256>>>(                     // 4 <- profile
        xb, w1b, xh1h, asrc1, adst1, als1, ald1, NV, 256);

    // ---- side stream: CSR build (runs concurrently with the above) ----
    deg_init<<<(NV + TB - 1) / TB, TB, 0, sCsr>>>();
    deg_hist<<<(EE + TB - 1) / TB, TB, 0, sCsr>>>(ei);
    scan_k<<<1, 1024, 0, sCsr>>>();
    scatter_k<<<(ET + TB - 1) / TB, TB, 0, sCsr>>>(ei);
    cudaEventRecord(ev1, sCsr);

    // ---- join + rest of main chain ----
    cudaStreamWaitEvent(0, ev1, 0);
    gat_agg1<<<(NV * 64 + TB - 1) / TB, TB>>>(xh1h, als1, ald1, b1, h2b);

    gemm_mma<1><<<dim3(1, (NV + 127) / 128), 256>>>(
        h2b, w2b, xh2h, asrc2, adst2, als2, ald2, NV, 64);
    gat_agg2<<<(NV * 32 + TB - 1) / TB, TB>>>(xh2h, als2, ald2, b2, out);
}

// round 13
// speedup vs baseline: 1.1374x; 1.1374x over previous
#include <cuda_runtime.h>
#include <cuda_bf16.h>
#include <cuda_fp16.h>
#include <math.h>
#include <cstdint>

#define NV 50000
#define EE 800000
#define ET (EE + NV)
#define HEADS 4
#define D1 256
#define KTOT 512

typedef unsigned long long ull;

// ---------------- scratch ------------------------------------------------------
__device__ __half g_xh1h[(size_t)NV * D1];
__device__ __half g_xh2h[(size_t)NV * 64];
__device__ __half g_xb[(size_t)NV * 512];      // x: [hi(256)|lo(256)] fp16
__device__ __half g_h2b[(size_t)NV * 512];     // h: [hi(256)|lo(256)] fp16
__device__ __half g_w1b[256 * KTOT];           // [n][k]: W repeated twice
__device__ __half g_w2b[64 * KTOT];
__device__ float g_als1[NV * HEADS], g_ald1[NV * HEADS];
__device__ float g_als2[NV], g_ald2[NV];
__device__ float g_t1[(size_t)ET * HEADS];
__device__ float g_t2[ET];
__device__ int g_rowptr[NV + 1], g_deg[NV], g_elist[ET];

// ---------------- helpers ------------------------------------------------------
__device__ __forceinline__ float lrelu(float v) { return v > 0.f ? v : 0.2f * v; }
__device__ __forceinline__ void edge_sd(const int* __restrict__ ei, int e, int& s, int& d) {
    if (e < EE) { s = ei[e]; d = ei[EE + e]; } else { s = e - EE; d = s; }
}
#define FMA2(acc, a, b) asm("fma.rn.f32x2 %0, %1, %2, %3;" : "=l"(acc) : "l"(a), "l"(b), "l"(acc))
#define PACK2(o, v)     asm("mov.b64 %0, {%1, %1};" : "=l"(o) : "r"(__float_as_uint(v)))
#define UNPACK2(l, h, i) asm("mov.b64 {%0, %1}, %2;" : "=r"(l), "=r"(h) : "l"(i))

__device__ __forceinline__ uint32_t smem_u32(const void* p) {
    uint32_t a;
    asm("{ .reg .u64 t; cvta.to.shared.u64 t, %1; cvt.u32.u64 %0, t; }" : "=r"(a) : "l"(p));
    return a;
}
#define CP16(dst, src) asm volatile("cp.async.ca.shared.global [%0], [%1], 16;" :: "r"(dst), "l"(src))
#define CPCOMMIT()     asm volatile("cp.async.commit_group;" ::: "memory")
#define CPWAIT(n)      asm volatile("cp.async.wait_group %0;" :: "n"(n) : "memory")

// ---------------- conversions ----------------------------------------------------
__global__ void convW(const float* __restrict__ W, __half* __restrict__ Bt, int Nc) {
    int i = blockIdx.x * blockDim.x + threadIdx.x;
    if (i >= 256 * Nc) return;
    int k = i / Nc, n = i % Nc;
    __half wh = __float2half_rn(W[k * Nc + n]);
    Bt[(size_t)n * KTOT + k] = wh;
    Bt[(size_t)n * KTOT + 256 + k] = wh;
}
__global__ void convX(const float* __restrict__ x, __half* __restrict__ xb) {
    int i = blockIdx.x * blockDim.x + threadIdx.x;
    if (i >= NV * 64) return;
    int node = i >> 6, c = (i & 63) * 4;
    float4 f = *(const float4*)&x[(size_t)node * 256 + c];
    float ff[4] = {f.x, f.y, f.z, f.w};
    __half hb[4], lb[4];
#pragma unroll
    for (int e = 0; e < 4; e++) {
        hb[e] = __float2half_rn(ff[e]);
        lb[e] = __float2half_rn(ff[e] - __half2float(hb[e]));
    }
    *(ull*)&xb[(size_t)node * 512 + c] = *(ull*)hb;
    *(ull*)&xb[(size_t)node * 512 + 256 + c] = *(ull*)lb;
}

// ---------------- CSR build --------------------------------------------------------
__global__ void deg_init() { int i = blockIdx.x * blockDim.x + threadIdx.x; if (i < NV) g_deg[i] = 1; }
__global__ void deg_hist(const int* __restrict__ ei) {
    int e = blockIdx.x * blockDim.x + threadIdx.x;
    if (e < EE) atomicAdd(&g_deg[ei[EE + e]], 1);
}
__global__ void scan_k() {
    __shared__ int ssum[1024];
    const int CH = (NV + 1023) / 1024;
    int t = threadIdx.x, base = t * CH, s = 0;
    for (int j = 0; j < CH; j++) { int i = base + j; if (i < NV) s += g_deg[i]; }
    ssum[t] = s; __syncthreads();
    for (int off = 1; off < 1024; off <<= 1) {
        int v = (t >= off) ? ssum[t - off] : 0;
        __syncthreads(); ssum[t] += v; __syncthreads();
    }
    int off = (t == 0) ? 0 : ssum[t - 1];
    for (int j = 0; j < CH; j++) {
        int i = base + j;
        if (i < NV) { int d = g_deg[i]; g_rowptr[i] = off; g_deg[i] = off; off += d; }
    }
    if (t == 0) g_rowptr[NV] = ET;
}
__global__ void scatter_k(const int* __restrict__ ei) {
    int e = blockIdx.x * blockDim.x + threadIdx.x;
    if (e >= ET) return;
    int s, d; edge_sd(ei, e, s, d);
    g_elist[atomicAdd(&g_deg[d], 1)] = s;
}

// ---------------- mma.sync fp16 GEMM + fused attention dots -------------------------
// C[M,NTOT] = A[M,512]*(Bt[N,512])^T, 16 stages of K=32, double buffered.
template <int H>
__global__ __launch_bounds__(256) void gemm_mma(
    const __half* __restrict__ Ab, const __half* __restrict__ Bt,
    __half* __restrict__ Ch, const float* __restrict__ asrc, const float* __restrict__ adst,
    float* __restrict__ als, float* __restrict__ ald, int M, int NTOT) {
    __shared__ __align__(16) __half sA[2][128 * 40];
    __shared__ __align__(16) __half sB[2][64 * 40];
    __shared__ float sdot[128][2];
    int tid = threadIdx.x, lane = tid & 31, w = tid >> 5;
    int wm = w & 3, wn = w >> 2;
    int rowBase = blockIdx.y * 128, n0 = blockIdx.x * 64;

    uint32_t sAa = smem_u32(&sA[0][0]);
    uint32_t sBa = smem_u32(&sB[0][0]);

    int arow = tid >> 1, aseg = (tid & 1) * 16;
    int brow = tid >> 2, bseg = (tid & 3) * 8;
    const __half* Asrc = Ab + (size_t)min(rowBase + arow, M - 1) * 512 + aseg;
    const __half* Bsrc = Bt + (size_t)(n0 + brow) * KTOT + bseg;
    uint32_t Adst = sAa + arow * 80 + aseg * 2;
    uint32_t Bdst = sBa + brow * 80 + bseg * 2;

#define ISSUE(s) do { \
    int _b = (s) & 1; int _k0 = (s) * 32; \
    CP16(Adst + _b * 10240, Asrc + _k0); \
    CP16(Adst + _b * 10240 + 16, Asrc + _k0 + 8); \
    CP16(Bdst + _b * 5120, Bsrc + _k0); \
} while (0)

    float acc[2][4][4];
#pragma unroll
    for (int i = 0; i < 2; i++)
#pragma unroll
        for (int j = 0; j < 4; j++)
#pragma unroll
            for (int q = 0; q < 4; q++) acc[i][j][q] = 0.f;

    ISSUE(0); CPCOMMIT();
    for (int s = 0; s < 16; s++) {
        if (s < 15) { ISSUE(s + 1); CPCOMMIT(); CPWAIT(1); }
        else        { CPWAIT(0); }
        __syncthreads();
        int b = s & 1;
        uint32_t baseA = sAa + b * 10240;
        uint32_t baseB = sBa + b * 5120;
#pragma unroll
        for (int kt = 0; kt < 2; kt++) {
            uint32_t a[2][4], bb[4][2];
#pragma unroll
            for (int mt = 0; mt < 2; mt++) {
                uint32_t addr = baseA + (wm * 32 + mt * 16 + (lane & 15)) * 80 +
                                kt * 32 + (lane >> 4) * 16;
                asm volatile("ldmatrix.sync.aligned.m8n8.x4.shared.b16 {%0,%1,%2,%3}, [%4];"
                             : "=r"(a[mt][0]), "=r"(a[mt][1]), "=r"(a[mt][2]), "=r"(a[mt][3])
                             : "r"(addr));
            }
#pragma unroll
            for (int nt = 0; nt < 4; nt++) {
                uint32_t addr = baseB + (wn * 32 + nt * 8 + (lane & 7)) * 80 +
                                kt * 32 + ((lane >> 3) & 1) * 16;
                asm volatile("ldmatrix.sync.aligned.m8n8.x2.shared.b16 {%0,%1}, [%2];"
                             : "=r"(bb[nt][0]), "=r"(bb[nt][1]) : "r"(addr));
            }
#pragma unroll
            for (int mt = 0; mt < 2; mt++)
#pragma unroll
                for (int nt = 0; nt < 4; nt++)
                    asm volatile(
                        "mma.sync.aligned.m16n8k16.row.col.f32.f16.f16.f32 "
                        "{%0,%1,%2,%3}, {%4,%5,%6,%7}, {%8,%9}, {%0,%1,%2,%3};"
                        : "+f"(acc[mt][nt][0]), "+f"(acc[mt][nt][1]),
                          "+f"(acc[mt][nt][2]), "+f"(acc[mt][nt][3])
                        : "r"(a[mt][0]), "r"(a[mt][1]), "r"(a[mt][2]), "r"(a[mt][3]),
                          "r"(bb[nt][0]), "r"(bb[nt][1]));
        }
        __syncthreads();
    }
#undef ISSUE

    sdot[tid >> 1][tid & 1] = 0.f;
    __syncthreads();
    int g = lane >> 2, tg = lane & 3;
    float as_[8], ad_[8];
#pragma unroll
    for (int nt = 0; nt < 4; nt++)
#pragma unroll
        for (int j = 0; j < 2; j++) {
            int col = n0 + wn * 32 + nt * 8 + tg * 2 + j;
            as_[nt * 2 + j] = asrc[col];
            ad_[nt * 2 + j] = adst[col];
        }
#pragma unroll
    for (int mt = 0; mt < 2; mt++) {
        int r0l = wm * 32 + mt * 16 + g, r1l = r0l + 8;
        int r0 = rowBase + r0l, r1 = rowBase + r1l;
        float s0 = 0.f, d0 = 0.f, s1 = 0.f, d1 = 0.f;
#pragma unroll
        for (int nt = 0; nt < 4; nt++) {
#pragma unroll
            for (int j = 0; j < 2; j++) {
                s0 += acc[mt][nt][j] * as_[nt * 2 + j];
                d0 += acc[mt][nt][j] * ad_[nt * 2 + j];
                s1 += acc[mt][nt][2 + j] * as_[nt * 2 + j];
                d1 += acc[mt][nt][2 + j] * ad_[nt * 2 + j];
            }
            int col = n0 + wn * 32 + nt * 8 + tg * 2;
            if (r0 < M) *(__half2*)&Ch[(size_t)r0 * NTOT + col] =
                __floats2half2_rn(acc[mt][nt][0], acc[mt][nt][1]);
            if (r1 < M) *(__half2*)&Ch[(size_t)r1 * NTOT + col] =
                __floats2half2_rn(acc[mt][nt][2], acc[mt][nt][3]);
        }
#pragma unroll
        for (int o = 1; o <= 2; o <<= 1) {
            s0 += __shfl_xor_sync(~0u, s0, o); d0 += __shfl_xor_sync(~0u, d0, o);
            s1 += __shfl_xor_sync(~0u, s1, o); d1 += __shfl_xor_sync(~0u, d1, o);
        }
        if (tg == 0) {
            atomicAdd(&sdot[r0l][0], s0); atomicAdd(&sdot[r0l][1], d0);
            atomicAdd(&sdot[r1l][0], s1); atomicAdd(&sdot[r1l][1], d1);
        }
    }
    __syncthreads();
    if (tid < 128) {
        int r = rowBase + tid;
        if (r < M) {
            int head = blockIdx.x;
            als[(size_t)r * H + head] = sdot[tid][0];
            ald[(size_t)r * H + head] = sdot[tid][1];
        }
    }
}

// ---------------- agg layer1: 2 warps/node, fixed-8 clamped chunks, fp16 gather ------
__global__ void gat_agg1(const __half* __restrict__ xh, const float* __restrict__ als,
                         const float* __restrict__ ald, const float* __restrict__ bias,
                         __half* __restrict__ h2b) {
    int gw = (blockIdx.x * blockDim.x + threadIdx.x) >> 5;
    int node = gw >> 1, hp = gw & 1;
    if (node >= NV) return;
    int lane = threadIdx.x & 31;
    int beg = g_rowptr[node], end = g_rowptr[node + 1];
    float2 av = *(const float2*)&ald[node * 4 + 2 * hp];

    float d0 = 0.f, d1 = 0.f;
    for (int j = beg + lane; j < end; j += 32) {
        float2 a = *(const float2*)&als[g_elist[j] * 4 + 2 * hp];
        float t0 = __expf(lrelu(a.x + av.x)), t1 = __expf(lrelu(a.y + av.y));
        *(float2*)&g_t1[(size_t)j * 4 + 2 * hp] = make_float2(t0, t1);
        d0 += t0; d1 += t1;
    }
#pragma unroll
    for (int o = 16; o; o >>= 1) {
        d0 += __shfl_xor_sync(~0u, d0, o);
        d1 += __shfl_xor_sync(~0u, d1, o);
    }
    int hl = lane >> 4;
    int myhead = hp * 2 + hl;
    float myinv = 1.f / ((hl ? d1 : d0) + 1e-16f);
    __syncwarp();

    int c0 = hp * 128 + lane * 4;
    ull acc[2] = {0, 0};
    for (int j0 = beg; j0 < end; j0 += 32) {
        int cnt = min(32, end - j0);
        int sv = g_elist[j0 + min(lane, cnt - 1)];
        for (int k0 = 0; k0 < cnt; k0 += 8) {
#pragma unroll
            for (int q = 0; q < 8; q++) {
                int k = k0 + q;
                int kc = min(k, cnt - 1);
                int s = __shfl_sync(~0u, sv, kc);
                float t = g_t1[(size_t)(j0 + kc) * 4 + myhead];
                t = (k < cnt) ? t : 0.f;
                ull wd; PACK2(wd, t);
                uint2 v = *(const uint2*)(xh + (size_t)s * 256 + c0);
                float2 f0 = __half22float2(*(__half2*)&v.x);
                float2 f1 = __half22float2(*(__half2*)&v.y);
                FMA2(acc[0], *(ull*)&f0, wd);
                FMA2(acc[1], *(ull*)&f1, wd);
            }
        }
    }
    float o[4];
#pragma unroll
    for (int i = 0; i < 2; i++) {
        unsigned lo_, hi_;
        UNPACK2(lo_, hi_, acc[i]);
        float v0 = __uint_as_float(lo_) * myinv + bias[c0 + 2 * i];
        float v1 = __uint_as_float(hi_) * myinv + bias[c0 + 2 * i + 1];
        o[2 * i] = v0 > 0.f ? v0 : expm1f(v0);
        o[2 * i + 1] = v1 > 0.f ? v1 : expm1f(v1);
    }
    __half hb[4], lb[4];
#pragma unroll
    for (int i = 0; i < 4; i++) {
        hb[i] = __float2half_rn(o[i]);
        lb[i] = __float2half_rn(o[i] - __half2float(hb[i]));
    }
    *(ull*)&h2b[(size_t)node * 512 + c0] = *(ull*)hb;
    *(ull*)&h2b[(size_t)node * 512 + 256 + c0] = *(ull*)lb;
}

// ---------------- agg layer2: warp/node, fixed-8 clamped chunks, fp16 gather ---------
__global__ void gat_agg2(const __half* __restrict__ xh, const float* __restrict__ als,
                         const float* __restrict__ ald, const float* __restrict__ bias,
                         float* __restrict__ out) {
    int node = (blockIdx.x * blockDim.x + threadIdx.x) >> 5;
    if (node >= NV) return;
    int lane = threadIdx.x & 31;
    int beg = g_rowptr[node], end = g_rowptr[node + 1];
    float av = ald[node];

    float den = 0.f;
    for (int j = beg + lane; j < end; j += 32) {
        float t = __expf(lrelu(als[g_elist[j]] + av));
        g_t2[j] = t; den += t;
    }
#pragma unroll
    for (int o = 16; o; o >>= 1) den += __shfl_xor_sync(~0u, den, o);
    float inv = 1.f / (den + 1e-16f);
    __syncwarp();

    ull acc = 0;
    for (int j0 = beg; j0 < end; j0 += 32) {
        int cnt = min(32, end - j0);
        int cl = min(lane, cnt - 1);
        int sv = g_elist[j0 + cl];
        float tv = g_t2[j0 + cl];
        for (int k0 = 0; k0 < cnt; k0 += 8) {
#pragma unroll
            for (int q = 0; q < 8; q++) {
                int k = k0 + q;
                int kc = min(k, cnt - 1);
                int s = __shfl_sync(~0u, sv, kc);
                float t = __shfl_sync(~0u, tv, kc);
                t = (k < cnt) ? t : 0.f;
                ull wd; PACK2(wd, t);
                uint32_t v = *(const uint32_t*)(xh + (size_t)s * 64 + lane * 2);
                float2 f = __half22float2(*(__half2*)&v);
                FMA2(acc, *(ull*)&f, wd);
            }
        }
    }
    unsigned lo, hi;
    UNPACK2(lo, hi, acc);
    int c = lane * 2;
    float v0 = __uint_as_float(lo) * inv + bias[c];
    float v1 = __uint_as_float(hi) * inv + bias[c + 1];
    *(float2*)(out + (size_t)node * 64 + c) =
        make_float2(v0 > 0.f ? v0 : expm1f(v0), v1 > 0.f ? v1 : expm1f(v1));
}

// ---------------- launch ---------------------------------------------------------------
extern "C" void kernel_launch(void* const* d_in, const int* in_sizes, int n_in,
                              void* d_out, int out_size) {
    const float* x     = (const float*)d_in[0];
    const int*   ei    = (const int*)d_in[1];
    const float* W1    = (const float*)d_in[2];
    const float* asrc1 = (const float*)d_in[3];
    const float* adst1 = (const float*)d_in[4];
    const float* b1    = (const float*)d_in[5];
    const float* W2    = (const float*)d_in[6];
    const float* asrc2 = (const float*)d_in[7];
    const float* adst2 = (const float*)d_in[8];
    const float* b2    = (const float*)d_in[9];
    float* out = (float*)d_out;

    float *als1, *ald1, *als2, *ald2;
    __half *xh1h, *xh2h, *w1b, *w2b, *xb, *h2b;
    cudaGetSymbolAddress((void**)&xh1h, g_xh1h);
    cudaGetSymbolAddress((void**)&xh2h, g_xh2h);
    cudaGetSymbolAddress((void**)&als1, g_als1);
    cudaGetSymbolAddress((void**)&ald1, g_ald1);
    cudaGetSymbolAddress((void**)&als2, g_als2);
    cudaGetSymbolAddress((void**)&ald2, g_ald2);
    cudaGetSymbolAddress((void**)&w1b, g_w1b);
    cudaGetSymbolAddress((void**)&w2b, g_w2b);
    cudaGetSymbolAddress((void**)&xb, g_xb);
    cudaGetSymbolAddress((void**)&h2b, g_h2b);

    static cudaStream_t sCsr = nullptr;
    static cudaEvent_t ev0 = nullptr, ev1 = nullptr;
    if (!sCsr) {
        cudaStreamCreateWithFlags(&sCsr, cudaStreamNonBlocking);
        cudaEventCreateWithFlags(&ev0, cudaEventDisableTiming);
        cudaEventCreateWithFlags(&ev1, cudaEventDisableTiming);
    }

    const int TB = 256;

    cudaEventRecord(ev0, 0);
    cudaStreamWaitEvent(sCsr, ev0, 0);

    // main chain first; gemm1 is the 4th launch (profiled slot)
    convX<<<(NV * 64 + TB - 1) / TB, TB>>>(x, xb);                       // 1
    convW<<<(256 * 256 + TB - 1) / TB, TB>>>(W1, w1b, 256);              // 2
    convW<<<(256 * 64 + TB - 1) / TB, TB>>>(W2, w2b, 64);                // 3
    gemm_mma<4><<<dim3(4, (NV + 127) / 128), 256>>>(                     // 4 <- profile
        xb, w1b, xh1h, asrc1, adst1, als1, ald1, NV, 256);

    // side stream: CSR build (concurrent)
    deg_init<<<(NV + TB - 1) / TB, TB, 0, sCsr>>>();
    deg_hist<<<(EE + TB - 1) / TB, TB, 0, sCsr>>>(ei);
    scan_k<<<1, 1024, 0, sCsr>>>();
    scatter_k<<<(ET + TB - 1) / TB, TB, 0, sCsr>>>(ei);
    cudaEventRecord(ev1, sCsr);

    cudaStreamWaitEvent(0, ev1, 0);
    gat_agg1<<<(NV * 64 + TB - 1) / TB, TB>>>(xh1h, als1, ald1, b1, h2b);

    gemm_mma<1><<<dim3(1, (NV + 127) / 128), 256>>>(
        h2b, w2b, xh2h, asrc2, adst2, als2, ald2, NV, 64);
    gat_agg2<<<(NV * 32 + TB - 1) / TB, TB>>>(xh2h, als2, ald2, b2, out);
}

// round 14
// speedup vs baseline: 1.1394x; 1.0018x over previous
#include <cuda_runtime.h>
#include <cuda_bf16.h>
#include <cuda_fp16.h>
#include <math.h>
#include <cstdint>

#define NV 50000
#define EE 800000
#define ET (EE + NV)
#define HEADS 4
#define D1 256
#define KTOT 512

typedef unsigned long long ull;

// ---------------- scratch ------------------------------------------------------
__device__ __half g_xh1h[(size_t)NV * D1];
__device__ __half g_xh2h[(size_t)NV * 64];
__device__ __half g_xb[(size_t)NV * 512];      // x: [hi(256)|lo(256)] fp16
__device__ __half g_h2b[(size_t)NV * 512];     // h: [hi(256)|lo(256)] fp16
__device__ __half g_w1b[256 * KTOT];
__device__ __half g_w2b[64 * KTOT];
__device__ float g_als1[NV * HEADS], g_ald1[NV * HEADS];
__device__ float g_als2[NV], g_ald2[NV];
__device__ float g_t1[(size_t)ET * HEADS];
__device__ float g_t2[ET];
__device__ int g_rowptr[NV + 1], g_deg[NV], g_elist[ET];

// ---------------- helpers ------------------------------------------------------
__device__ __forceinline__ float lrelu(float v) { return v > 0.f ? v : 0.2f * v; }
__device__ __forceinline__ void edge_sd(const int* __restrict__ ei, int e, int& s, int& d) {
    if (e < EE) { s = ei[e]; d = ei[EE + e]; } else { s = e - EE; d = s; }
}
#define FMA2(acc, a, b) asm("fma.rn.f32x2 %0, %1, %2, %3;" : "=l"(acc) : "l"(a), "l"(b), "l"(acc))
#define PACK2(o, v)     asm("mov.b64 %0, {%1, %1};" : "=l"(o) : "r"(__float_as_uint(v)))
#define UNPACK2(l, h, i) asm("mov.b64 {%0, %1}, %2;" : "=r"(l), "=r"(h) : "l"(i))

__device__ __forceinline__ uint32_t smem_u32(const void* p) {
    uint32_t a;
    asm("{ .reg .u64 t; cvta.to.shared.u64 t, %1; cvt.u32.u64 %0, t; }" : "=r"(a) : "l"(p));
    return a;
}
#define CP16(dst, src) asm volatile("cp.async.ca.shared.global [%0], [%1], 16;" :: "r"(dst), "l"(src))
#define CPCOMMIT()     asm volatile("cp.async.commit_group;" ::: "memory")
#define CPWAIT(n)      asm volatile("cp.async.wait_group %0;" :: "n"(n) : "memory")

// ---------------- conversions ----------------------------------------------------
__global__ void convW(const float* __restrict__ W, __half* __restrict__ Bt, int Nc) {
    int i = blockIdx.x * blockDim.x + threadIdx.x;
    if (i >= 256 * Nc) return;
    int k = i / Nc, n = i % Nc;
    __half wh = __float2half_rn(W[k * Nc + n]);
    Bt[(size_t)n * KTOT + k] = wh;
    Bt[(size_t)n * KTOT + 256 + k] = wh;
}
__global__ void convX(const float* __restrict__ x, __half* __restrict__ xb) {
    int i = blockIdx.x * blockDim.x + threadIdx.x;
    if (i >= NV * 64) return;
    int node = i >> 6, c = (i & 63) * 4;
    float4 f = *(const float4*)&x[(size_t)node * 256 + c];
    float ff[4] = {f.x, f.y, f.z, f.w};
    __half hb[4], lb[4];
#pragma unroll
    for (int e = 0; e < 4; e++) {
        hb[e] = __float2half_rn(ff[e]);
        lb[e] = __float2half_rn(ff[e] - __half2float(hb[e]));
    }
    *(ull*)&xb[(size_t)node * 512 + c] = *(ull*)hb;
    *(ull*)&xb[(size_t)node * 512 + 256 + c] = *(ull*)lb;
}

// ---------------- CSR build --------------------------------------------------------
__global__ void deg_init() { int i = blockIdx.x * blockDim.x + threadIdx.x; if (i < NV) g_deg[i] = 1; }
__global__ void deg_hist(const int* __restrict__ ei) {
    int e = blockIdx.x * blockDim.x + threadIdx.x;
    if (e < EE) atomicAdd(&g_deg[ei[EE + e]], 1);
}
__global__ void scan_k() {
    __shared__ int ssum[1024];
    const int CH = (NV + 1023) / 1024;
    int t = threadIdx.x, base = t * CH, s = 0;
    for (int j = 0; j < CH; j++) { int i = base + j; if (i < NV) s += g_deg[i]; }
    ssum[t] = s; __syncthreads();
    for (int off = 1; off < 1024; off <<= 1) {
        int v = (t >= off) ? ssum[t - off] : 0;
        __syncthreads(); ssum[t] += v; __syncthreads();
    }
    int off = (t == 0) ? 0 : ssum[t - 1];
    for (int j = 0; j < CH; j++) {
        int i = base + j;
        if (i < NV) { int d = g_deg[i]; g_rowptr[i] = off; g_deg[i] = off; off += d; }
    }
    if (t == 0) g_rowptr[NV] = ET;
}
__global__ void scatter_k(const int* __restrict__ ei) {
    int e = blockIdx.x * blockDim.x + threadIdx.x;
    if (e >= ET) return;
    int s, d; edge_sd(ei, e, s, d);
    g_elist[atomicAdd(&g_deg[d], 1)] = s;
}

// ---------------- mma.sync fp16 GEMM + fused attention dots -------------------------
template <int H>
__global__ __launch_bounds__(256) void gemm_mma(
    const __half* __restrict__ Ab, const __half* __restrict__ Bt,
    __half* __restrict__ Ch, const float* __restrict__ asrc, const float* __restrict__ adst,
    float* __restrict__ als, float* __restrict__ ald, int M, int NTOT) {
    __shared__ __align__(16) __half sA[2][128 * 40];
    __shared__ __align__(16) __half sB[2][64 * 40];
    __shared__ float sdot[128][2];
    int tid = threadIdx.x, lane = tid & 31, w = tid >> 5;
    int wm = w & 3, wn = w >> 2;
    int rowBase = blockIdx.y * 128, n0 = blockIdx.x * 64;

    uint32_t sAa = smem_u32(&sA[0][0]);
    uint32_t sBa = smem_u32(&sB[0][0]);

    int arow = tid >> 1, aseg = (tid & 1) * 16;
    int brow = tid >> 2, bseg = (tid & 3) * 8;
    const __half* Asrc = Ab + (size_t)min(rowBase + arow, M - 1) * 512 + aseg;
    const __half* Bsrc = Bt + (size_t)(n0 + brow) * KTOT + bseg;
    uint32_t Adst = sAa + arow * 80 + aseg * 2;
    uint32_t Bdst = sBa + brow * 80 + bseg * 2;

#define ISSUE(s) do { \
    int _b = (s) & 1; int _k0 = (s) * 32; \
    CP16(Adst + _b * 10240, Asrc + _k0); \
    CP16(Adst + _b * 10240 + 16, Asrc + _k0 + 8); \
    CP16(Bdst + _b * 5120, Bsrc + _k0); \
} while (0)

    float acc[2][4][4];
#pragma unroll
    for (int i = 0; i < 2; i++)
#pragma unroll
        for (int j = 0; j < 4; j++)
#pragma unroll
            for (int q = 0; q < 4; q++) acc[i][j][q] = 0.f;

    ISSUE(0); CPCOMMIT();
    for (int s = 0; s < 16; s++) {
        if (s < 15) { ISSUE(s + 1); CPCOMMIT(); CPWAIT(1); }
        else        { CPWAIT(0); }
        __syncthreads();
        int b = s & 1;
        uint32_t baseA = sAa + b * 10240;
        uint32_t baseB = sBa + b * 5120;
#pragma unroll
        for (int kt = 0; kt < 2; kt++) {
            uint32_t a[2][4], bb[4][2];
#pragma unroll
            for (int mt = 0; mt < 2; mt++) {
                uint32_t addr = baseA + (wm * 32 + mt * 16 + (lane & 15)) * 80 +
                                kt * 32 + (lane >> 4) * 16;
                asm volatile("ldmatrix.sync.aligned.m8n8.x4.shared.b16 {%0,%1,%2,%3}, [%4];"
                             : "=r"(a[mt][0]), "=r"(a[mt][1]), "=r"(a[mt][2]), "=r"(a[mt][3])
                             : "r"(addr));
            }
            // B: pairs of nt tiles in one ldmatrix.x4 (lanes 0-7:nt/k0, 8-15:nt/k1,
            // 16-23:nt+1/k0, 24-31:nt+1/k1)
#pragma unroll
            for (int nt = 0; nt < 4; nt += 2) {
                uint32_t addr = baseB +
                    (wn * 32 + (nt + ((lane >> 4) & 1)) * 8 + (lane & 7)) * 80 +
                    kt * 32 + ((lane >> 3) & 1) * 16;
                asm volatile("ldmatrix.sync.aligned.m8n8.x4.shared.b16 {%0,%1,%2,%3}, [%4];"
                             : "=r"(bb[nt][0]), "=r"(bb[nt][1]),
                               "=r"(bb[nt + 1][0]), "=r"(bb[nt + 1][1])
                             : "r"(addr));
            }
#pragma unroll
            for (int mt = 0; mt < 2; mt++)
#pragma unroll
                for (int nt = 0; nt < 4; nt++)
                    asm volatile(
                        "mma.sync.aligned.m16n8k16.row.col.f32.f16.f16.f32 "
                        "{%0,%1,%2,%3}, {%4,%5,%6,%7}, {%8,%9}, {%0,%1,%2,%3};"
                        : "+f"(acc[mt][nt][0]), "+f"(acc[mt][nt][1]),
                          "+f"(acc[mt][nt][2]), "+f"(acc[mt][nt][3])
                        : "r"(a[mt][0]), "r"(a[mt][1]), "r"(a[mt][2]), "r"(a[mt][3]),
                          "r"(bb[nt][0]), "r"(bb[nt][1]));
        }
        __syncthreads();
    }
#undef ISSUE

    sdot[tid >> 1][tid & 1] = 0.f;
    __syncthreads();
    int g = lane >> 2, tg = lane & 3;
    float as_[8], ad_[8];
#pragma unroll
    for (int nt = 0; nt < 4; nt++)
#pragma unroll
        for (int j = 0; j < 2; j++) {
            int col = n0 + wn * 32 + nt * 8 + tg * 2 + j;
            as_[nt * 2 + j] = asrc[col];
            ad_[nt * 2 + j] = adst[col];
        }
#pragma unroll
    for (int mt = 0; mt < 2; mt++) {
        int r0l = wm * 32 + mt * 16 + g, r1l = r0l + 8;
        int r0 = rowBase + r0l, r1 = rowBase + r1l;
        float s0 = 0.f, d0 = 0.f, s1 = 0.f, d1 = 0.f;
#pragma unroll
        for (int nt = 0; nt < 4; nt++) {
#pragma unroll
            for (int j = 0; j < 2; j++) {
                s0 += acc[mt][nt][j] * as_[nt * 2 + j];
                d0 += acc[mt][nt][j] * ad_[nt * 2 + j];
                s1 += acc[mt][nt][2 + j] * as_[nt * 2 + j];
                d1 += acc[mt][nt][2 + j] * ad_[nt * 2 + j];
            }
            int col = n0 + wn * 32 + nt * 8 + tg * 2;
            if (r0 < M) *(__half2*)&Ch[(size_t)r0 * NTOT + col] =
                __floats2half2_rn(acc[mt][nt][0], acc[mt][nt][1]);
            if (r1 < M) *(__half2*)&Ch[(size_t)r1 * NTOT + col] =
                __floats2half2_rn(acc[mt][nt][2], acc[mt][nt][3]);
        }
#pragma unroll
        for (int o = 1; o <= 2; o <<= 1) {
            s0 += __shfl_xor_sync(~0u, s0, o); d0 += __shfl_xor_sync(~0u, d0, o);
            s1 += __shfl_xor_sync(~0u, s1, o); d1 += __shfl_xor_sync(~0u, d1, o);
        }
        if (tg == 0) {
            atomicAdd(&sdot[r0l][0], s0); atomicAdd(&sdot[r0l][1], d0);
            atomicAdd(&sdot[r1l][0], s1); atomicAdd(&sdot[r1l][1], d1);
        }
    }
    __syncthreads();
    if (tid < 128) {
        int r = rowBase + tid;
        if (r < M) {
            int head = blockIdx.x;
            als[(size_t)r * H + head] = sdot[tid][0];
            ald[(size_t)r * H + head] = sdot[tid][1];
        }
    }
}

// ---------------- agg layer1: 2 warps/node, fixed-8 clamped chunks, fp16 gather ------
__global__ void gat_agg1(const __half* __restrict__ xh, const float* __restrict__ als,
                         const float* __restrict__ ald, const float* __restrict__ bias,
                         __half* __restrict__ h2b) {
    int gw = (blockIdx.x * blockDim.x + threadIdx.x) >> 5;
    int node = gw >> 1, hp = gw & 1;
    if (node >= NV) return;
    int lane = threadIdx.x & 31;
    int beg = g_rowptr[node], end = g_rowptr[node + 1];
    float2 av = *(const float2*)&ald[node * 4 + 2 * hp];

    float d0 = 0.f, d1 = 0.f;
    for (int j = beg + lane; j < end; j += 32) {
        float2 a = *(const float2*)&als[g_elist[j] * 4 + 2 * hp];
        float t0 = __expf(lrelu(a.x + av.x)), t1 = __expf(lrelu(a.y + av.y));
        *(float2*)&g_t1[(size_t)j * 4 + 2 * hp] = make_float2(t0, t1);
        d0 += t0; d1 += t1;
    }
#pragma unroll
    for (int o = 16; o; o >>= 1) {
        d0 += __shfl_xor_sync(~0u, d0, o);
        d1 += __shfl_xor_sync(~0u, d1, o);
    }
    int hl = lane >> 4;
    int myhead = hp * 2 + hl;
    float myinv = 1.f / ((hl ? d1 : d0) + 1e-16f);
    __syncwarp();

    int c0 = hp * 128 + lane * 4;
    ull acc[2] = {0, 0};
    for (int j0 = beg; j0 < end; j0 += 32) {
        int cnt = min(32, end - j0);
        int sv = g_elist[j0 + min(lane, cnt - 1)];
        for (int k0 = 0; k0 < cnt; k0 += 8) {
#pragma unroll
            for (int q = 0; q < 8; q++) {
                int k = k0 + q;
                int kc = min(k, cnt - 1);
                int s = __shfl_sync(~0u, sv, kc);
                float t = g_t1[(size_t)(j0 + kc) * 4 + myhead];
                t = (k < cnt) ? t : 0.f;
                ull wd; PACK2(wd, t);
                uint2 v = *(const uint2*)(xh + (size_t)s * 256 + c0);
                float2 f0 = __half22float2(*(__half2*)&v.x);
                float2 f1 = __half22float2(*(__half2*)&v.y);
                FMA2(acc[0], *(ull*)&f0, wd);
                FMA2(acc[1], *(ull*)&f1, wd);
            }
        }
    }
    float o[4];
#pragma unroll
    for (int i = 0; i < 2; i++) {
        unsigned lo_, hi_;
        UNPACK2(lo_, hi_, acc[i]);
        float v0 = __uint_as_float(lo_) * myinv + bias[c0 + 2 * i];
        float v1 = __uint_as_float(hi_) * myinv + bias[c0 + 2 * i + 1];
        o[2 * i] = v0 > 0.f ? v0 : expm1f(v0);
        o[2 * i + 1] = v1 > 0.f ? v1 : expm1f(v1);
    }
    __half hb[4], lb[4];
#pragma unroll
    for (int i = 0; i < 4; i++) {
        hb[i] = __float2half_rn(o[i]);
        lb[i] = __float2half_rn(o[i] - __half2float(hb[i]));
    }
    *(ull*)&h2b[(size_t)node * 512 + c0] = *(ull*)hb;
    *(ull*)&h2b[(size_t)node * 512 + 256 + c0] = *(ull*)lb;
}

// ---------------- agg layer2: warp/node, fixed-8 clamped chunks, fp16 gather ---------
__global__ void gat_agg2(const __half* __restrict__ xh, const float* __restrict__ als,
                         const float* __restrict__ ald, const float* __restrict__ bias,
                         float* __restrict__ out) {
    int node = (blockIdx.x * blockDim.x + threadIdx.x) >> 5;
    if (node >= NV) return;
    int lane = threadIdx.x & 31;
    int beg = g_rowptr[node], end = g_rowptr[node + 1];
    float av = ald[node];

    float den = 0.f;
    for (int j = beg + lane; j < end; j += 32) {
        float t = __expf(lrelu(als[g_elist[j]] + av));
        g_t2[j] = t; den += t;
    }
#pragma unroll
    for (int o = 16; o; o >>= 1) den += __shfl_xor_sync(~0u, den, o);
    float inv = 1.f / (den + 1e-16f);
    __syncwarp();

    ull acc = 0;
    for (int j0 = beg; j0 < end; j0 += 32) {
        int cnt = min(32, end - j0);
        int cl = min(lane, cnt - 1);
        int sv = g_elist[j0 + cl];
        float tv = g_t2[j0 + cl];
        for (int k0 = 0; k0 < cnt; k0 += 8) {
#pragma unroll
            for (int q = 0; q < 8; q++) {
                int k = k0 + q;
                int kc = min(k, cnt - 1);
                int s = __shfl_sync(~0u, sv, kc);
                float t = __shfl_sync(~0u, tv, kc);
                t = (k < cnt) ? t : 0.f;
                ull wd; PACK2(wd, t);
                uint32_t v = *(const uint32_t*)(xh + (size_t)s * 64 + lane * 2);
                float2 f = __half22float2(*(__half2*)&v);
                FMA2(acc, *(ull*)&f, wd);
            }
        }
    }
    unsigned lo, hi;
    UNPACK2(lo, hi, acc);
    int c = lane * 2;
    float v0 = __uint_as_float(lo) * inv + bias[c];
    float v1 = __uint_as_float(hi) * inv + bias[c + 1];
    *(float2*)(out + (size_t)node * 64 + c) =
        make_float2(v0 > 0.f ? v0 : expm1f(v0), v1 > 0.f ? v1 : expm1f(v1));
}

// ---------------- launch ---------------------------------------------------------------
extern "C" void kernel_launch(void* const* d_in, const int* in_sizes, int n_in,
                              void* d_out, int out_size) {
    const float* x     = (const float*)d_in[0];
    const int*   ei    = (const int*)d_in[1];
    const float* W1    = (const float*)d_in[2];
    const float* asrc1 = (const float*)d_in[3];
    const float* adst1 = (const float*)d_in[4];
    const float* b1    = (const float*)d_in[5];
    const float* W2    = (const float*)d_in[6];
    const float* asrc2 = (const float*)d_in[7];
    const float* adst2 = (const float*)d_in[8];
    const float* b2    = (const float*)d_in[9];
    float* out = (float*)d_out;

    float *als1, *ald1, *als2, *ald2;
    __half *xh1h, *xh2h, *w1b, *w2b, *xb, *h2b;
    cudaGetSymbolAddress((void**)&xh1h, g_xh1h);
    cudaGetSymbolAddress((void**)&xh2h, g_xh2h);
    cudaGetSymbolAddress((void**)&als1, g_als1);
    cudaGetSymbolAddress((void**)&ald1, g_ald1);
    cudaGetSymbolAddress((void**)&als2, g_als2);
    cudaGetSymbolAddress((void**)&ald2, g_ald2);
    cudaGetSymbolAddress((void**)&w1b, g_w1b);
    cudaGetSymbolAddress((void**)&w2b, g_w2b);
    cudaGetSymbolAddress((void**)&xb, g_xb);
    cudaGetSymbolAddress((void**)&h2b, g_h2b);

    static cudaStream_t sCsr = nullptr;
    static cudaEvent_t ev0 = nullptr, ev1 = nullptr;
    if (!sCsr) {
        cudaStreamCreateWithFlags(&sCsr, cudaStreamNonBlocking);
        cudaEventCreateWithFlags(&ev0, cudaEventDisableTiming);
        cudaEventCreateWithFlags(&ev1, cudaEventDisableTiming);
    }

    const int TB = 256;

    cudaEventRecord(ev0, 0);
    cudaStreamWaitEvent(sCsr, ev0, 0);

    // main chain first; gemm1 is the 4th launch (profiled slot)
    convX<<<(NV * 64 + TB - 1) / TB, TB>>>(x, xb);                       // 1
    convW<<<(256 * 256 + TB - 1) / TB, TB>>>(W1, w1b, 256);              // 2
    convW<<<(256 * 64 + TB - 1) / TB, TB>>>(W2, w2b, 64);                // 3
    gemm_mma<4><<<dim3(4, (NV + 127) / 128), 256>>>(                     // 4 <- profile
        xb, w1b, xh1h, asrc1, adst1, als1, ald1, NV, 256);

    // side stream: CSR build (concurrent)
    deg_init<<<(NV + TB - 1) / TB, TB, 0, sCsr>>>();
    deg_hist<<<(EE + TB - 1) / TB, TB, 0, sCsr>>>(ei);
    scan_k<<<1, 1024, 0, sCsr>>>();
    scatter_k<<<(ET + TB - 1) / TB, TB, 0, sCsr>>>(ei);
    cudaEventRecord(ev1, sCsr);

    cudaStreamWaitEvent(0, ev1, 0);
    gat_agg1<<<(NV * 64 + TB - 1) / TB, TB>>>(xh1h, als1, ald1, b1, h2b);

    gemm_mma<1><<<dim3(1, (NV + 127) / 128), 256>>>(
        h2b, w2b, xh2h, asrc2, adst2, als2, ald2, NV, 64);
    gat_agg2<<<(NV * 32 + TB - 1) / TB, TB>>>(xh2h, als2, ald2, b2, out);
}